// round 4
// baseline (speedup 1.0000x reference)
#include <cuda_runtime.h>
#include <cuda_bf16.h>
#include <math.h>

// ---------------------------------------------------------------------------
// Problem constants
// ---------------------------------------------------------------------------
#define BATCH     2048
#define SDIM      64
#define ADIM      16
#define HID       256
#define TDIM      32
#define TSTEPS    100
#define CAT       112            // ADIM + TDIM + SDIM
#define RPC       8              // rows per CTA
#define NCTA      (BATCH / RPC)  // 256

typedef unsigned long long ull;

// ---------------------------------------------------------------------------
// Precomputed schedule + time embeddings (written by prolog kernel)
// ---------------------------------------------------------------------------
__device__ float g_temb[TSTEPS * TDIM];
__device__ float g_srac[TSTEPS];
__device__ float g_sracm1[TSTEPS];
__device__ float g_c1[TSTEPS];
__device__ float g_c2[TSTEPS];
__device__ float g_sigma[TSTEPS];

// ---------------------------------------------------------------------------
// f32x2 helpers
// ---------------------------------------------------------------------------
__device__ __forceinline__ void fma2(ull& d, ull a, ull b) {
    asm("fma.rn.f32x2 %0, %1, %2, %0;" : "+l"(d) : "l"(a), "l"(b));
}
__device__ __forceinline__ void unpack2(ull v, float& lo, float& hi) {
    asm("mov.b64 {%0, %1}, %2;" : "=f"(lo), "=f"(hi) : "l"(v));
}

// ---------------------------------------------------------------------------
// mish(x) = x * tanh(softplus(x))  (stable softplus, same as jax)
// ---------------------------------------------------------------------------
__device__ __forceinline__ float mishf(float x) {
    float sp = fmaxf(x, 0.0f) + log1pf(expf(-fabsf(x)));
    return x * tanhf(sp);
}

// ---------------------------------------------------------------------------
// Prolog: VP schedule in f64 + per-timestep time-MLP (batch-invariant).
// ---------------------------------------------------------------------------
__global__ void __launch_bounds__(256) prolog_kernel(
    const float* __restrict__ tW1, const float* __restrict__ tb1,
    const float* __restrict__ tW2, const float* __restrict__ tb2)
{
    const int tid = threadIdx.x;
    const int i   = blockIdx.x;

    if (i == 0 && tid == 0) {
        const double T = (double)TSTEPS, bmax = 10.0, bmin = 0.1;
        double ac = 1.0;
        for (int idx = 0; idx < TSTEPS; ++idx) {
            double t      = (double)(idx + 1);
            double alpha  = exp(-bmin / T - 0.5 * (bmax - bmin) * (2.0 * t - 1.0) / (T * T));
            double beta   = 1.0 - alpha;
            double acp    = ac;
            ac            = ac * alpha;
            g_srac[idx]   = (float)sqrt(1.0 / ac);
            g_sracm1[idx] = (float)sqrt(1.0 / ac - 1.0);
            g_c1[idx]     = (float)(beta * sqrt(acp) / (1.0 - ac));
            g_c2[idx]     = (float)((1.0 - acp) * sqrt(alpha) / (1.0 - ac));
            double pv     = beta * (1.0 - acp) / (1.0 - ac);
            if (pv < 1e-20) pv = 1e-20;
            g_sigma[idx]  = (float)exp(0.5 * log(pv));   // NOISE_RATIO = 1
        }
    }

    __shared__ float emb[TDIM];
    __shared__ float hid[HID];

    if (tid < TDIM) {
        int   j    = tid & 15;
        float freq = expf((float)j * (-logf(10000.0f) / 15.0f));
        float ang  = (float)i * freq;
        emb[tid]   = (tid < 16) ? sinf(ang) : cosf(ang);
    }
    __syncthreads();

    {
        float a = tb1[tid];
#pragma unroll
        for (int j = 0; j < TDIM; ++j)
            a = fmaf(emb[j], tW1[j * HID + tid], a);
        hid[tid] = mishf(a);
    }
    __syncthreads();

    if (tid < TDIM) {
        float a = tb2[tid];
#pragma unroll 8
        for (int h = 0; h < HID; ++h)
            a = fmaf(hid[h], tW2[h * TDIM + tid], a);
        g_temb[i * TDIM + tid] = a;
    }
}

// ---------------------------------------------------------------------------
// Dense layer, column-pair packed with dup-stored activations.
//   in  : smem [K][RPC] as float2{a,a}   (LDS.64 broadcast, zero packing)
//   W   : gmem [K][256]; adjacent col pair read as ulonglong2 via LDG.128
//   out : smem [256][RPC] float2{v,v}
// Thread = 1 row x 8 cols (4 col-pair accumulators).
// Per k: 1 LDS.64 + 2 LDG.128 + 4 FFMA2 — no ALU packs.
// ---------------------------------------------------------------------------
template <int K, bool MISH>
__device__ __forceinline__ void dense8(
    const float2* __restrict__ in,
    const float*  __restrict__ W,
    const float*  __restrict__ b,
    float2* __restrict__ out)
{
    const int tid = threadIdx.x;
    const int cg  = tid >> 3;       // col group 0..31
    const int r   = tid & 7;        // row 0..7
    const int c0  = cg * 8;

    ull acc0 = 0, acc1 = 0, acc2 = 0, acc3 = 0;
    const ull* __restrict__ inp = (const ull*)in;    // element (k*RPC + r)

#pragma unroll 4
    for (int k = 0; k < K; ++k) {
        const ull a = inp[k * RPC + r];                                  // {a,a}
        const ulonglong2 w01 = *(const ulonglong2*)(W + k * HID + c0);   // cols c0..c0+3
        const ulonglong2 w23 = *(const ulonglong2*)(W + k * HID + c0 + 4);
        fma2(acc0, a, w01.x);
        fma2(acc1, a, w01.y);
        fma2(acc2, a, w23.x);
        fma2(acc3, a, w23.y);
    }

    float lo, hi;
    unpack2(acc0, lo, hi);
    { float v = lo + b[c0 + 0]; if (MISH) v = mishf(v); out[(c0 + 0) * RPC + r] = make_float2(v, v); }
    { float v = hi + b[c0 + 1]; if (MISH) v = mishf(v); out[(c0 + 1) * RPC + r] = make_float2(v, v); }
    unpack2(acc1, lo, hi);
    { float v = lo + b[c0 + 2]; if (MISH) v = mishf(v); out[(c0 + 2) * RPC + r] = make_float2(v, v); }
    { float v = hi + b[c0 + 3]; if (MISH) v = mishf(v); out[(c0 + 3) * RPC + r] = make_float2(v, v); }
    unpack2(acc2, lo, hi);
    { float v = lo + b[c0 + 4]; if (MISH) v = mishf(v); out[(c0 + 4) * RPC + r] = make_float2(v, v); }
    { float v = hi + b[c0 + 5]; if (MISH) v = mishf(v); out[(c0 + 5) * RPC + r] = make_float2(v, v); }
    unpack2(acc3, lo, hi);
    { float v = lo + b[c0 + 6]; if (MISH) v = mishf(v); out[(c0 + 6) * RPC + r] = make_float2(v, v); }
    { float v = hi + b[c0 + 7]; if (MISH) v = mishf(v); out[(c0 + 7) * RPC + r] = make_float2(v, v); }
    __syncthreads();
}

// ---------------------------------------------------------------------------
// Fused sampler: one CTA owns 8 rows for all 100 steps; x lives dup-packed
// inside the layer-1 input buffer (features 0..15).
// ---------------------------------------------------------------------------
__global__ void __launch_bounds__(256, 2) sampler_kernel(
    const float* __restrict__ state,
    const float* __restrict__ x_init,
    const float* __restrict__ noise,     // [TSTEPS][BATCH][ADIM]
    const float* __restrict__ W1, const float* __restrict__ b1,
    const float* __restrict__ W2, const float* __restrict__ b2,
    const float* __restrict__ W3, const float* __restrict__ b3,
    const float* __restrict__ W4, const float* __restrict__ b4,
    float* __restrict__ out)
{
    __shared__ __align__(16) float2 a0[CAT * RPC];   // [112][8] dup  7.0 KB
    __shared__ __align__(16) float2 hA[HID * RPC];   // [256][8] dup 16.0 KB
    __shared__ __align__(16) float2 hB[HID * RPC];   // [256][8] dup 16.0 KB
    __shared__ float red[256];                       // layer4 partials 1 KB

    const int tid  = threadIdx.x;
    const int row0 = blockIdx.x * RPC;

    // ---- one-time fills (dup-stored) ----
    if (tid < 128) {                      // x: 16 feats x 8 rows
        int f = tid >> 3, r = tid & 7;
        float v = x_init[(row0 + r) * ADIM + f];
        a0[f * RPC + r] = make_float2(v, v);
    }
#pragma unroll
    for (int p = 0; p < 2; ++p) {         // state: 64 feats x 8 rows = 512
        int idx = tid + p * 256;
        int f = idx >> 3, r = idx & 7;
        float v = state[(row0 + r) * SDIM + f];
        a0[(ADIM + TDIM + f) * RPC + r] = make_float2(v, v);
    }

    // ---- 100 diffusion steps, fully CTA-local ----
    for (int s = 0; s < TSTEPS; ++s) {
        const int i = TSTEPS - 1 - s;

        {   // temb: 32 feats x 8 rows (row-invariant)
            int f = tid >> 3, r = tid & 7;
            float t = g_temb[i * TDIM + f];
            a0[(ADIM + f) * RPC + r] = make_float2(t, t);
        }
        __syncthreads();

        dense8<CAT, true>(a0, W1, b1, hA);
        dense8<HID, true>(hA, W2, b2, hB);
        dense8<HID, true>(hB, W3, b3, hA);

        // ---- layer 4 (256 -> 16): k split in 2 chunks of 128 ----
        {
            const int kc = tid >> 7;            // 0..1
            const int rr = (tid >> 4) & 7;      // row
            const int c  = tid & 15;            // out col
            float acc = 0.0f;
            const int k0 = kc * 128;
#pragma unroll 8
            for (int k = k0; k < k0 + 128; ++k)
                acc = fmaf(hA[k * RPC + rr].x, W4[k * ADIM + c], acc);
            red[tid] = acc;
        }
        __syncthreads();

        // ---- reduce + posterior update (128 threads: row rr, col c) ----
        if (tid < 128) {
            const int rr = (tid >> 4) & 7;
            const int c  = tid & 15;
            float eps = red[tid] + red[tid + 128] + b4[c];

            const float x_old = a0[c * RPC + rr].x;
            const float sr = g_srac[i], srm = g_sracm1[i];
            const float c1 = g_c1[i],   c2  = g_c2[i];

            float xr = fminf(fmaxf(sr * x_old - srm * eps, -1.0f), 1.0f);
            float mn = c1 * xr + c2 * x_old;

            if (i > 0) {
                const float sg = g_sigma[i];
                float nz = noise[(size_t)s * BATCH * ADIM + (row0 + rr) * ADIM + c];
                float xn = fmaf(sg, nz, mn);
                a0[c * RPC + rr] = make_float2(xn, xn);
            } else {
                out[(row0 + rr) * ADIM + c] = fminf(fmaxf(mn, -1.0f), 1.0f);
            }
        }
        __syncthreads();
    }
}

// ---------------------------------------------------------------------------
// kernel_launch: prolog + ONE fused sampler kernel.
// ---------------------------------------------------------------------------
extern "C" void kernel_launch(void* const* d_in, const int* in_sizes, int n_in,
                              void* d_out, int out_size)
{
    const float* state  = (const float*)d_in[0];
    const float* x_init = (const float*)d_in[1];
    const float* noise  = (const float*)d_in[2];
    const float* tW1    = (const float*)d_in[3];
    const float* tb1    = (const float*)d_in[4];
    const float* tW2    = (const float*)d_in[5];
    const float* tb2    = (const float*)d_in[6];
    const float* W1     = (const float*)d_in[7];
    const float* b1     = (const float*)d_in[8];
    const float* W2     = (const float*)d_in[9];
    const float* b2     = (const float*)d_in[10];
    const float* W3     = (const float*)d_in[11];
    const float* b3     = (const float*)d_in[12];
    const float* W4     = (const float*)d_in[13];
    const float* b4     = (const float*)d_in[14];
    float* out          = (float*)d_out;

    prolog_kernel<<<TSTEPS, 256>>>(tW1, tb1, tW2, tb2);
    sampler_kernel<<<NCTA, 256>>>(state, x_init, noise,
                                  W1, b1, W2, b2, W3, b3, W4, b4, out);
}

// round 5
// speedup vs baseline: 1.6204x; 1.6204x over previous
#include <cuda_runtime.h>
#include <cuda_bf16.h>
#include <math.h>

// ---------------------------------------------------------------------------
// Problem constants
// ---------------------------------------------------------------------------
#define BATCH     2048
#define SDIM      64
#define ADIM      16
#define HID       256
#define TDIM      32
#define TSTEPS    100
#define CAT       112            // ADIM + TDIM + SDIM
#define RPC       16             // rows per CTA
#define NRP       8              // row-pairs per CTA
#define NCTA      (BATCH / RPC)  // 128
#define NTHR      512            // 128 col-threads x 4 k-chunks

typedef unsigned long long ull;

// ---------------------------------------------------------------------------
// Precomputed tables
// ---------------------------------------------------------------------------
__device__ float g_temb[TSTEPS * TDIM];
__device__ float g_srac[TSTEPS];
__device__ float g_sracm1[TSTEPS];
__device__ float g_c1[TSTEPS];
__device__ float g_c2[TSTEPS];
__device__ float g_sigma[TSTEPS];

// duplicated weights: Wd[k*cols + c] = {w, w}
__device__ __align__(16) ull g_W1d[CAT * HID];   // 229 KB
__device__ __align__(16) ull g_W2d[HID * HID];   // 512 KB
__device__ __align__(16) ull g_W3d[HID * HID];   // 512 KB
__device__ __align__(16) ull g_W4d[HID * ADIM];  //  32 KB

// ---------------------------------------------------------------------------
// f32x2 helpers
// ---------------------------------------------------------------------------
__device__ __forceinline__ ull pack2(float lo, float hi) {
    ull r; asm("mov.b64 %0, {%1, %2};" : "=l"(r) : "f"(lo), "f"(hi)); return r;
}
__device__ __forceinline__ void unpack2(ull v, float& lo, float& hi) {
    asm("mov.b64 {%0, %1}, %2;" : "=f"(lo), "=f"(hi) : "l"(v));
}
__device__ __forceinline__ void fma2(ull& d, ull a, ull b) {
    asm("fma.rn.f32x2 %0, %1, %2, %0;" : "+l"(d) : "l"(a), "l"(b));
}
__device__ __forceinline__ ull add2(ull a, ull b) {
    ull r; asm("add.rn.f32x2 %0, %1, %2;" : "=l"(r) : "l"(a), "l"(b)); return r;
}

__device__ __forceinline__ float mishf(float x) {
    float sp = fmaxf(x, 0.0f) + log1pf(expf(-fabsf(x)));
    return x * tanhf(sp);
}

// ---------------------------------------------------------------------------
// Setup: build duplicated weight tables (once per launch, deterministic)
// ---------------------------------------------------------------------------
__global__ void setup_dup_kernel(const float* __restrict__ W1,
                                 const float* __restrict__ W2,
                                 const float* __restrict__ W3,
                                 const float* __restrict__ W4)
{
    int idx = blockIdx.x * blockDim.x + threadIdx.x;
    const int N1 = CAT * HID, N2 = HID * HID, N4 = HID * ADIM;
    if (idx < N1)            { float w = W1[idx]; g_W1d[idx] = pack2(w, w); }
    if (idx < N2)            { float w = W2[idx]; g_W2d[idx] = pack2(w, w); }
    if (idx < N2)            { float w = W3[idx]; g_W3d[idx] = pack2(w, w); }
    if (idx < N4)            { float w = W4[idx]; g_W4d[idx] = pack2(w, w); }
}

// ---------------------------------------------------------------------------
// Prolog: VP schedule in f64 + per-timestep time-MLP (batch-invariant).
// ---------------------------------------------------------------------------
__global__ void __launch_bounds__(256) prolog_kernel(
    const float* __restrict__ tW1, const float* __restrict__ tb1,
    const float* __restrict__ tW2, const float* __restrict__ tb2)
{
    const int tid = threadIdx.x;
    const int i   = blockIdx.x;

    if (i == 0 && tid == 0) {
        const double T = (double)TSTEPS, bmax = 10.0, bmin = 0.1;
        double ac = 1.0;
        for (int idx = 0; idx < TSTEPS; ++idx) {
            double t      = (double)(idx + 1);
            double alpha  = exp(-bmin / T - 0.5 * (bmax - bmin) * (2.0 * t - 1.0) / (T * T));
            double beta   = 1.0 - alpha;
            double acp    = ac;
            ac            = ac * alpha;
            g_srac[idx]   = (float)sqrt(1.0 / ac);
            g_sracm1[idx] = (float)sqrt(1.0 / ac - 1.0);
            g_c1[idx]     = (float)(beta * sqrt(acp) / (1.0 - ac));
            g_c2[idx]     = (float)((1.0 - acp) * sqrt(alpha) / (1.0 - ac));
            double pv     = beta * (1.0 - acp) / (1.0 - ac);
            if (pv < 1e-20) pv = 1e-20;
            g_sigma[idx]  = (float)exp(0.5 * log(pv));
        }
    }

    __shared__ float emb[TDIM];
    __shared__ float hid[HID];

    if (tid < TDIM) {
        int   j    = tid & 15;
        float freq = expf((float)j * (-logf(10000.0f) / 15.0f));
        float ang  = (float)i * freq;
        emb[tid]   = (tid < 16) ? sinf(ang) : cosf(ang);
    }
    __syncthreads();
    {
        float a = tb1[tid];
#pragma unroll
        for (int j = 0; j < TDIM; ++j)
            a = fmaf(emb[j], tW1[j * HID + tid], a);
        hid[tid] = mishf(a);
    }
    __syncthreads();
    if (tid < TDIM) {
        float a = tb2[tid];
#pragma unroll 8
        for (int h = 0; h < HID; ++h)
            a = fmaf(hid[h], tW2[h * TDIM + tid], a);
        g_temb[i * TDIM + tid] = a;
    }
}

// ---------------------------------------------------------------------------
// Dense layer, thread tile = 8 row-pairs x 2 cols, 4-way k-split.
//   in  : smem ull[K][NRP]   row-pair packed activations
//   Wd  : gmem dup table ull[K][256]
//   out : smem ull[256][NRP] (may alias `in` — all reads finish before sync)
// Per k: 4 LDS.128 (broadcast) + 1 LDG.128 + 16 FFMA2.
// k-split partials merged with 3 serialized staged adds into out; mish is
// applied by ALL threads in a spread pass.
// ---------------------------------------------------------------------------
template <int K>
__device__ __forceinline__ void dense_ip(
    const ull* __restrict__ in,
    const ull* __restrict__ Wd,
    const float* __restrict__ b,
    ull* __restrict__ out,
    int cg, int ks, int tid)
{
    const int c0 = cg * 2;
    ull acc[8][2];
#pragma unroll
    for (int rp = 0; rp < NRP; ++rp) { acc[rp][0] = 0; acc[rp][1] = 0; }

    const int kn = K / 4;
    const int kb = ks * kn;

#pragma unroll 4
    for (int kk = 0; kk < kn; ++kk) {
        const int k = kb + kk;
        const ulonglong2 a01 = *(const ulonglong2*)(in + k * NRP + 0);
        const ulonglong2 a23 = *(const ulonglong2*)(in + k * NRP + 2);
        const ulonglong2 a45 = *(const ulonglong2*)(in + k * NRP + 4);
        const ulonglong2 a67 = *(const ulonglong2*)(in + k * NRP + 6);
        const ulonglong2 w   = *(const ulonglong2*)(Wd + k * HID + c0);
        fma2(acc[0][0], a01.x, w.x);  fma2(acc[0][1], a01.x, w.y);
        fma2(acc[1][0], a01.y, w.x);  fma2(acc[1][1], a01.y, w.y);
        fma2(acc[2][0], a23.x, w.x);  fma2(acc[2][1], a23.x, w.y);
        fma2(acc[3][0], a23.y, w.x);  fma2(acc[3][1], a23.y, w.y);
        fma2(acc[4][0], a45.x, w.x);  fma2(acc[4][1], a45.x, w.y);
        fma2(acc[5][0], a45.y, w.x);  fma2(acc[5][1], a45.y, w.y);
        fma2(acc[6][0], a67.x, w.x);  fma2(acc[6][1], a67.x, w.y);
        fma2(acc[7][0], a67.y, w.x);  fma2(acc[7][1], a67.y, w.y);
    }
    __syncthreads();                         // all reads of `in` done

    ull* o = out + c0 * NRP;                 // 16 contiguous ull (2 cols x 8 rp)

    if (ks == 0) {
#pragma unroll
        for (int cc = 0; cc < 2; ++cc)
#pragma unroll
            for (int rp = 0; rp < NRP; ++rp) o[cc * NRP + rp] = acc[rp][cc];
    }
    __syncthreads();
    if (ks == 1) {
#pragma unroll
        for (int cc = 0; cc < 2; ++cc)
#pragma unroll
            for (int rp = 0; rp < NRP; ++rp)
                o[cc * NRP + rp] = add2(o[cc * NRP + rp], acc[rp][cc]);
    }
    __syncthreads();
    if (ks == 2) {
#pragma unroll
        for (int cc = 0; cc < 2; ++cc)
#pragma unroll
            for (int rp = 0; rp < NRP; ++rp)
                o[cc * NRP + rp] = add2(o[cc * NRP + rp], acc[rp][cc]);
    }
    __syncthreads();
    if (ks == 3) {
        const ull b0 = pack2(b[c0], b[c0]);
        const ull b1 = pack2(b[c0 + 1], b[c0 + 1]);
#pragma unroll
        for (int rp = 0; rp < NRP; ++rp) {
            o[rp]       = add2(add2(o[rp],       acc[rp][0]), b0);
            o[NRP + rp] = add2(add2(o[NRP + rp], acc[rp][1]), b1);
        }
    }
    __syncthreads();

    // spread mish: each of 512 threads activates 4 ull (8 values)
    {
        ull* p = out + tid * 4;
#pragma unroll
        for (int j = 0; j < 4; ++j) {
            float lo, hi; unpack2(p[j], lo, hi);
            p[j] = pack2(mishf(lo), mishf(hi));
        }
    }
    __syncthreads();
}

// ---------------------------------------------------------------------------
// Fused sampler: CTA owns 16 rows for all 100 steps.
// ---------------------------------------------------------------------------
__global__ void __launch_bounds__(NTHR, 1) sampler_kernel(
    const float* __restrict__ state,
    const float* __restrict__ x_init,
    const float* __restrict__ noise,
    const float* __restrict__ b1, const float* __restrict__ b2,
    const float* __restrict__ b3, const float* __restrict__ b4,
    float* __restrict__ out)
{
    __shared__ __align__(16) ull a0[CAT * NRP];        //  7.0 KB  (layer-1 input)
    __shared__ __align__(16) ull hbuf[HID * NRP];      // 16.0 KB  (layers 1-3, in-place)
    __shared__ __align__(16) ull red4[NRP * ADIM * 4]; //  4.0 KB  (L4 partials)

    const int tid  = threadIdx.x;
    const int cg   = tid & 127;
    const int ks   = tid >> 7;
    const int row0 = blockIdx.x * RPC;

    // ---- one-time fills (row-pair packed) ----
    if (tid < 128) {                       // x: 16 feats x 8 rp
        int f = tid >> 3, rp = tid & 7;
        a0[f * NRP + rp] = pack2(x_init[(row0 + 2 * rp)     * ADIM + f],
                                 x_init[(row0 + 2 * rp + 1) * ADIM + f]);
    }
    {                                      // state: 64 feats x 8 rp = 512
        int f = tid >> 3, rp = tid & 7;
        a0[(ADIM + TDIM + f) * NRP + rp] =
            pack2(state[(row0 + 2 * rp)     * SDIM + f],
                  state[(row0 + 2 * rp + 1) * SDIM + f]);
    }

    for (int s = 0; s < TSTEPS; ++s) {
        const int i = TSTEPS - 1 - s;

        if (tid < 256) {                   // temb: 32 feats x 8 rp
            int f = tid >> 3, rp = tid & 7;
            float t = g_temb[i * TDIM + f];
            a0[(ADIM + f) * NRP + rp] = pack2(t, t);
        }
        __syncthreads();

        dense_ip<CAT>(a0,   g_W1d, b1, hbuf, cg, ks, tid);
        dense_ip<HID>(hbuf, g_W2d, b2, hbuf, cg, ks, tid);
        dense_ip<HID>(hbuf, g_W3d, b3, hbuf, cg, ks, tid);

        // ---- layer 4 (256 -> 16): thread = (rp, c, ks) ----
        {
            const int c  = tid & 15;
            const int rp = (tid >> 4) & 7;
            const int k4 = tid >> 7;       // k-chunk
            ull acc = 0;
            const int kb = k4 * 64;
#pragma unroll 4
            for (int kk = 0; kk < 64; ++kk) {
                const int k = kb + kk;
                fma2(acc, hbuf[k * NRP + rp], g_W4d[k * ADIM + c]);
            }
            red4[(rp * ADIM + c) * 4 + k4] = acc;
        }
        __syncthreads();

        // ---- reduce + posterior (128 threads: rp, c) ----
        if (tid < 128) {
            const int rp = tid >> 4, c = tid & 15;
            const ull* r = red4 + (rp * ADIM + c) * 4;
            ull e = add2(add2(r[0], r[1]), add2(r[2], r[3]));
            float e0, e1; unpack2(e, e0, e1);
            const float bb = b4[c];
            e0 += bb; e1 += bb;

            float x0, x1; unpack2(a0[c * NRP + rp], x0, x1);
            const float sr = g_srac[i], srm = g_sracm1[i];
            const float c1 = g_c1[i],   c2  = g_c2[i];

            float r0 = fminf(fmaxf(sr * x0 - srm * e0, -1.0f), 1.0f);
            float r1 = fminf(fmaxf(sr * x1 - srm * e1, -1.0f), 1.0f);
            float m0 = c1 * r0 + c2 * x0;
            float m1 = c1 * r1 + c2 * x1;

            if (i > 0) {
                const float sg = g_sigma[i];
                const float* nz = noise + (size_t)s * BATCH * ADIM;
                float n0 = nz[(row0 + 2 * rp)     * ADIM + c];
                float n1 = nz[(row0 + 2 * rp + 1) * ADIM + c];
                a0[c * NRP + rp] = pack2(fmaf(sg, n0, m0), fmaf(sg, n1, m1));
            } else {
                out[(row0 + 2 * rp)     * ADIM + c] = fminf(fmaxf(m0, -1.0f), 1.0f);
                out[(row0 + 2 * rp + 1) * ADIM + c] = fminf(fmaxf(m1, -1.0f), 1.0f);
            }
        }
        __syncthreads();
    }
}

// ---------------------------------------------------------------------------
// kernel_launch
// ---------------------------------------------------------------------------
extern "C" void kernel_launch(void* const* d_in, const int* in_sizes, int n_in,
                              void* d_out, int out_size)
{
    const float* state  = (const float*)d_in[0];
    const float* x_init = (const float*)d_in[1];
    const float* noise  = (const float*)d_in[2];
    const float* tW1    = (const float*)d_in[3];
    const float* tb1    = (const float*)d_in[4];
    const float* tW2    = (const float*)d_in[5];
    const float* tb2    = (const float*)d_in[6];
    const float* W1     = (const float*)d_in[7];
    const float* b1     = (const float*)d_in[8];
    const float* W2     = (const float*)d_in[9];
    const float* b2     = (const float*)d_in[10];
    const float* W3     = (const float*)d_in[11];
    const float* b3     = (const float*)d_in[12];
    const float* W4     = (const float*)d_in[13];
    const float* b4     = (const float*)d_in[14];
    float* out          = (float*)d_out;

    setup_dup_kernel<<<(HID * HID + 511) / 512, 512>>>(W1, W2, W3, W4);
    prolog_kernel<<<TSTEPS, 256>>>(tW1, tb1, tW2, tb2);
    sampler_kernel<<<NCTA, NTHR>>>(state, x_init, noise,
                                   b1, b2, b3, b4, out);
}